// round 2
// baseline (speedup 1.0000x reference)
#include <cuda_runtime.h>
#include <cstdint>

#define Bb   16
#define Cc   256
#define Pp   3136
#define Hh   56
#define Ww   56
#define S_   224
#define R_   16
#define KK   33
#define NPIX (Bb * S_ * S_)       // 802816
#define SDSTR 20                  // padded smem row stride (floats), 80B = 5x16B

// ---------------- scratch (static device arrays; no runtime allocation) ----
__device__ float g_delta[Pp * Cc * Bb];  // [p][c*16+b]  (51.4 MB)
__device__ float g_dist[Bb * Pp];        // [B,56,56]
__device__ float g_up[NPIX];
__device__ float g_tmp[NPIX];
__device__ float g_gw[KK];
__device__ int   g_minbits;
__device__ int   g_maxbits;

// ---------------- init: gaussian weights + min/max seeds -------------------
__global__ void k_init() {
    if (threadIdx.x == 0) {
        float w[KK];
        float s = 0.f;
        #pragma unroll
        for (int i = 0; i < KK; i++) {
            float x = (float)(i - R_) * 0.25f;     // x/sigma, sigma=4
            w[i] = expf(-0.5f * x * x);
            s += w[i];
        }
        float inv = 1.f / s;
        #pragma unroll
        for (int i = 0; i < KK; i++) g_gw[i] = w[i] * inv;
        g_minbits = 0x7f7fffff;   // +FLT_MAX  (scores >= 0 -> int-ordered)
        g_maxbits = 0;            // +0.0f
    }
}

// ---------------- stage 0: transpose emb -> delta[p][c*16+b] ----------------
// Coalesced on both sides; fuses the mean subtraction.
#define PT 32
#define CT 16
__global__ void k_transpose(const float* __restrict__ emb,
                            const float* __restrict__ means,
                            float* __restrict__ gdelta)
{
    __shared__ float ts[PT][CT * 16 + 1];   // stride 257 -> conflict-free both phases
    const int pb = blockIdx.x * PT;
    const int cb = blockIdx.y * CT;
    const int t = threadIdx.x;              // 256
    const int w = t >> 5, l = t & 31;

    // read: row r = ci*16+b (256 rows), 32 consecutive p per row (128B coalesced)
    #pragma unroll 4
    for (int j = 0; j < 32; j++) {
        int r  = (w << 5) + j;
        int ci = r >> 4, b = r & 15;
        ts[l][r] = emb[((size_t)(b * Cc + cb + ci)) * Pp + pb + l];
    }
    __syncthreads();

    // write: per p, 256 contiguous floats at gdelta[p*4096 + cb*16 + cf]
    #pragma unroll 4
    for (int j = 0; j < 32; j++) {
        int g  = t + 256 * j;         // 8192 floats total
        int pl = g >> 8;              // 256 floats per p
        int cf = g & 255;
        int ci = cf >> 4;
        float m = means[(size_t)(pb + pl) * Cc + cb + ci];
        gdelta[((size_t)(pb + pl)) * (Cc * Bb) + (size_t)cb * 16 + cf] =
            ts[pl][cf] - m;
    }
}

// ---------------- stage 1: mahalanobis (symmetric, upper-triangle) ---------
// q[b] = 2 * sum_d delta[b,d] * ( 0.5*M[d,d]*delta[b,d] + sum_{c<d} M[c,d]*delta[b,c] )
// 128 threads/CTA; thread owns adjacent columns d0=base+2l, d1=d0+1.
// Column blocks rotated across warps by blockIdx to balance SMSPs.
#define FMA2(acc, mm, dd) \
    asm("fma.rn.f32x2 %0, %1, %2, %0;" : "+l"(acc) : "l"(mm), "l"(dd))

#define MMABODY(mvx, mvy, rowptr)                                          \
  { unsigned long long mx, my;                                             \
    asm("mov.b64 %0, {%1, %1};" : "=l"(mx) : "f"(mvx));                    \
    asm("mov.b64 %0, {%1, %1};" : "=l"(my) : "f"(mvy));                    \
    const ulonglong2* rr = (const ulonglong2*)(rowptr);                    \
    ulonglong2 r0 = rr[0], r1 = rr[1], r2 = rr[2], r3 = rr[3];             \
    FMA2(accA[0], mx, r0.x); FMA2(accA[1], mx, r0.y);                      \
    FMA2(accA[2], mx, r1.x); FMA2(accA[3], mx, r1.y);                      \
    FMA2(accA[4], mx, r2.x); FMA2(accA[5], mx, r2.y);                      \
    FMA2(accA[6], mx, r3.x); FMA2(accA[7], mx, r3.y);                      \
    FMA2(accB[0], my, r0.x); FMA2(accB[1], my, r0.y);                      \
    FMA2(accB[2], my, r1.x); FMA2(accB[3], my, r1.y);                      \
    FMA2(accB[4], my, r2.x); FMA2(accB[5], my, r2.y);                      \
    FMA2(accB[6], my, r3.x); FMA2(accB[7], my, r3.y); }

__global__ void __launch_bounds__(128, 5)
k_mahal(const float* __restrict__ gdelta,   // [p][c*16+b]
        const float* __restrict__ icov,     // [P, C, C]
        float* __restrict__ dist)           // [B, P]
{
    const int p = blockIdx.x;
    const int t = threadIdx.x;              // 128
    const int w = t >> 5, l = t & 31;

    __shared__ __align__(16) float sd[Cc * SDSTR];   // delta rows, padded stride
    __shared__ float wsum[4][Bb];

    // coalesced load of delta tile (16KB) into padded smem rows
    {
        const float* src = gdelta + (size_t)p * (Cc * Bb);
        #pragma unroll
        for (int j = 0; j < 8; j++) {
            int fi = (t + 128 * j) << 2;        // float index, float4 granules
            int c = fi >> 4, b = fi & 15;
            float4 v = *(const float4*)(src + fi);
            *(float4*)&sd[c * SDSTR + b] = v;
        }
    }
    __syncthreads();

    const int blk = (w + blockIdx.x) & 3;       // rotate blocks across SMSPs
    const int d0  = (blk << 6) + (l << 1);      // d1 = d0 + 1
    const int cp  = (blk << 5) + l;             // column-pair index for float2 load
    const float2* M2 = (const float2*)(icov + (size_t)p * (Cc * Cc));

    unsigned long long accA[8], accB[8];
    #pragma unroll
    for (int j = 0; j < 8; j++) { accA[j] = 0ull; accB[j] = 0ull; }

    const int cmain = blk << 6;

    // main loop: strictly above the block -> no predicates, full warp active
    #pragma unroll 2
    for (int c = 0; c < cmain; c++) {
        float2 mv = M2[c * 128 + cp];           // 256B/warp coalesced
        MMABODY(mv.x, mv.y, &sd[c * SDSTR]);
    }
    // tail: 64 rows covering the diagonal block, predicated
    #pragma unroll 2
    for (int c = cmain; c < cmain + 64; c++) {
        float2 mv = make_float2(0.f, 0.f);
        if (c <= d0 + 1) mv = M2[c * 128 + cp];
        if (c >= d0) {
            mv.x = (c == d0) ? 0.5f * mv.x : 0.f;
            if (c == d0 + 1) mv.y *= 0.5f;
        }
        MMABODY(mv.x, mv.y, &sd[c * SDSTR]);
    }

    // q[b] = dA[b]*sA[b] + dB[b]*sB[b]
    float q[Bb];
    #pragma unroll
    for (int j = 0; j < 8; j++) {
        float2 fa = *(float2*)&accA[j];
        float2 fb = *(float2*)&accB[j];
        float2 dA = *(const float2*)&sd[d0 * SDSTR + 2 * j];
        float2 dB = *(const float2*)&sd[(d0 + 1) * SDSTR + 2 * j];
        q[2 * j]     = fa.x * dA.x + fb.x * dB.x;
        q[2 * j + 1] = fa.y * dA.y + fb.y * dB.y;
    }

    // reduce over 128 threads
    #pragma unroll
    for (int off = 16; off > 0; off >>= 1) {
        #pragma unroll
        for (int b = 0; b < Bb; b++)
            q[b] += __shfl_xor_sync(0xffffffffu, q[b], off);
    }
    if (l == 0) {
        #pragma unroll
        for (int b = 0; b < Bb; b++) wsum[w][b] = q[b];
    }
    __syncthreads();
    if (t < Bb) {
        float v = wsum[0][t] + wsum[1][t] + wsum[2][t] + wsum[3][t];
        dist[t * Pp + p] = sqrtf(2.f * v);      // x2 for symmetric half
    }
}

// ---------------- stage 2: bilinear 56 -> 224 (align_corners=False) --------
__global__ void k_resize(const float* __restrict__ dist, float* __restrict__ out)
{
    int idx = blockIdx.x * blockDim.x + threadIdx.x;
    if (idx >= NPIX) return;
    int X = idx % S_;
    int Y = (idx / S_) % S_;
    int b = idx / (S_ * S_);

    float fy = (float)Y * 0.25f - 0.375f;
    float fx = (float)X * 0.25f - 0.375f;
    int y0 = (int)floorf(fy); float wy = fy - (float)y0;
    int x0 = (int)floorf(fx); float wx = fx - (float)x0;
    int y0c = max(y0, 0), y1c = min(y0 + 1, Hh - 1);
    int x0c = max(x0, 0), x1c = min(x0 + 1, Ww - 1);

    const float* d = dist + b * Pp;
    float v00 = d[y0c * Ww + x0c], v01 = d[y0c * Ww + x1c];
    float v10 = d[y1c * Ww + x0c], v11 = d[y1c * Ww + x1c];
    float v0 = v00 + (v01 - v00) * wx;
    float v1 = v10 + (v11 - v10) * wx;
    out[idx] = v0 + (v1 - v0) * wy;
}

// symmetric padding (numpy 'symmetric' == scipy reflect), radius < 224
__device__ __forceinline__ int symi(int i) {
    i = (i < 0) ? (-1 - i) : i;
    i = (i >= S_) ? (2 * S_ - 1 - i) : i;
    return i;
}

// ---------------- stage 3a: gaussian blur along H ---------------------------
__global__ void k_blurH(const float* __restrict__ in, float* __restrict__ out)
{
    int idx = blockIdx.x * blockDim.x + threadIdx.x;
    if (idx >= NPIX) return;
    int X = idx % S_;
    int Y = (idx / S_) % S_;
    int b = idx / (S_ * S_);
    const float* base = in + b * S_ * S_;
    float v = 0.f;
    #pragma unroll
    for (int k = 0; k < KK; k++) {
        int y = symi(Y + k - R_);
        v = fmaf(g_gw[k], base[y * S_ + X], v);
    }
    out[idx] = v;
}

// ---------------- stage 3b: blur along W + global min/max -------------------
__global__ void k_blurW(const float* __restrict__ in, float* __restrict__ out)
{
    int idx = blockIdx.x * blockDim.x + threadIdx.x;
    int X = idx % S_;
    int Y = (idx / S_) % S_;
    int b = idx / (S_ * S_);
    const float* base = in + b * S_ * S_ + Y * S_;
    float v = 0.f;
    #pragma unroll
    for (int k = 0; k < KK; k++) {
        int x = symi(X + k - R_);
        v = fmaf(g_gw[k], base[x], v);
    }
    out[idx] = v;

    // block min/max (NPIX % 256 == 0 -> all threads valid)
    float mn = v, mx = v;
    #pragma unroll
    for (int off = 16; off > 0; off >>= 1) {
        mn = fminf(mn, __shfl_xor_sync(0xffffffffu, mn, off));
        mx = fmaxf(mx, __shfl_xor_sync(0xffffffffu, mx, off));
    }
    __shared__ float smn[8], smx[8];
    int warp = threadIdx.x >> 5, lane = threadIdx.x & 31;
    if (lane == 0) { smn[warp] = mn; smx[warp] = mx; }
    __syncthreads();
    if (threadIdx.x == 0) {
        float bmn = smn[0], bmx = smx[0];
        #pragma unroll
        for (int w = 1; w < 8; w++) {
            bmn = fminf(bmn, smn[w]);
            bmx = fmaxf(bmx, smx[w]);
        }
        atomicMin(&g_minbits, __float_as_int(bmn));   // values >= 0
        atomicMax(&g_maxbits, __float_as_int(bmx));
    }
}

// ---------------- stage 4: normalize ----------------------------------------
__global__ void k_norm(float* __restrict__ out)
{
    int idx = blockIdx.x * blockDim.x + threadIdx.x;
    if (idx >= NPIX) return;
    float mn = __int_as_float(g_minbits);
    float mx = __int_as_float(g_maxbits);
    out[idx] = (out[idx] - mn) / (mx - mn);
}

// ---------------- launcher ---------------------------------------------------
extern "C" void kernel_launch(void* const* d_in, const int* in_sizes, int n_in,
                              void* d_out, int out_size)
{
    const float* emb   = (const float*)d_in[0];   // [16, 256, 3136]
    const float* means = (const float*)d_in[1];   // [3136, 256]
    const float* icov  = (const float*)d_in[2];   // [3136, 256, 256]
    float* out = (float*)d_out;                   // [16, 224, 224] float32

    float *delta = nullptr, *dist = nullptr, *up = nullptr, *tmp = nullptr;
    cudaGetSymbolAddress((void**)&delta, g_delta);
    cudaGetSymbolAddress((void**)&dist,  g_dist);
    cudaGetSymbolAddress((void**)&up,    g_up);
    cudaGetSymbolAddress((void**)&tmp,   g_tmp);

    const int nb = NPIX / 256;
    k_init<<<1, 32>>>();
    k_transpose<<<dim3(Pp / PT, Cc / CT), 256>>>(emb, means, delta);
    k_mahal<<<Pp, 128>>>(delta, icov, dist);
    k_resize<<<nb, 256>>>(dist, up);
    k_blurH<<<nb, 256>>>(up, tmp);
    k_blurW<<<nb, 256>>>(tmp, out);
    k_norm<<<nb, 256>>>(out);
}

// round 4
// speedup vs baseline: 1.9144x; 1.9144x over previous
#include <cuda_runtime.h>
#include <cstdint>

#define Bb   16
#define Cc   256
#define Pp   3136
#define Hh   56
#define Ww   56
#define S_   224
#define R_   16
#define KK   33
#define NPIX (Bb * S_ * S_)       // 802816
#define SDSTR 20                  // padded smem row stride (floats), 80B

// ---------------- scratch (static device arrays; no runtime allocation) ----
__device__ float g_delta[Pp * Cc * Bb];  // [p][c*16+b]  (51.4 MB)
__device__ float g_dist[Bb * Pp];        // [B,56,56]
__device__ float g_up[NPIX];
__device__ float g_tmp[NPIX];
__device__ float g_gw[KK];
__device__ int   g_minbits;
__device__ int   g_maxbits;

// ---------------- init: gaussian weights + min/max seeds -------------------
__global__ void k_init() {
    if (threadIdx.x == 0) {
        float w[KK];
        float s = 0.f;
        #pragma unroll
        for (int i = 0; i < KK; i++) {
            float x = (float)(i - R_) * 0.25f;     // x/sigma, sigma=4
            w[i] = expf(-0.5f * x * x);
            s += w[i];
        }
        float inv = 1.f / s;
        #pragma unroll
        for (int i = 0; i < KK; i++) g_gw[i] = w[i] * inv;
        g_minbits = 0x7f7fffff;   // +FLT_MAX  (scores >= 0 -> int-ordered)
        g_maxbits = 0;            // +0.0f
    }
}

// ---------------- stage 0: transpose emb -> delta[p][c*16+b] ----------------
#define PT 32
#define CT 16
__global__ void k_transpose(const float* __restrict__ emb,
                            const float* __restrict__ means,
                            float* __restrict__ gdelta)
{
    __shared__ float ts[PT][CT * 16 + 1];
    const int pb = blockIdx.x * PT;
    const int cb = blockIdx.y * CT;
    const int t = threadIdx.x;              // 256
    const int w = t >> 5, l = t & 31;

    #pragma unroll 4
    for (int j = 0; j < 32; j++) {
        int r  = (w << 5) + j;
        int ci = r >> 4, b = r & 15;
        ts[l][r] = emb[((size_t)(b * Cc + cb + ci)) * Pp + pb + l];
    }
    __syncthreads();

    #pragma unroll 4
    for (int j = 0; j < 32; j++) {
        int g  = t + 256 * j;
        int pl = g >> 8;
        int cf = g & 255;
        int ci = cf >> 4;
        float m = means[(size_t)(pb + pl) * Cc + cb + ci];
        gdelta[((size_t)(pb + pl)) * (Cc * Bb) + (size_t)cb * 16 + cf] =
            ts[pl][cf] - m;
    }
}

// ---------------- stage 1: mahalanobis (symmetric upper triangle) ----------
// q[b] = 2 * sum_d delta[b,d]*(0.5*M[d,d]*delta[b,d] + sum_{c<d} M[c,d]*delta[b,c])
#define FMA2(acc, mm, dd) \
    asm("fma.rn.f32x2 %0, %1, %2, %0;" : "+l"(acc) : "l"(mm), "l"(dd))

#define MMABODY(mvx, mvy, rowptr)                                          \
  { unsigned long long mx, my;                                             \
    asm("mov.b64 %0, {%1, %1};" : "=l"(mx) : "f"(mvx));                    \
    asm("mov.b64 %0, {%1, %1};" : "=l"(my) : "f"(mvy));                    \
    const ulonglong2* rr = (const ulonglong2*)(rowptr);                    \
    ulonglong2 r0 = rr[0], r1 = rr[1], r2 = rr[2], r3 = rr[3];             \
    FMA2(accA[0], mx, r0.x); FMA2(accA[1], mx, r0.y);                      \
    FMA2(accA[2], mx, r1.x); FMA2(accA[3], mx, r1.y);                      \
    FMA2(accA[4], mx, r2.x); FMA2(accA[5], mx, r2.y);                      \
    FMA2(accA[6], mx, r3.x); FMA2(accA[7], mx, r3.y);                      \
    FMA2(accB[0], my, r0.x); FMA2(accB[1], my, r0.y);                      \
    FMA2(accB[2], my, r1.x); FMA2(accB[3], my, r1.y);                      \
    FMA2(accB[4], my, r2.x); FMA2(accB[5], my, r2.y);                      \
    FMA2(accB[6], my, r3.x); FMA2(accB[7], my, r3.y); }

__global__ void __launch_bounds__(128, 5)
k_mahal(const float* __restrict__ gdelta,   // [p][c*16+b]
        const float* __restrict__ icov,     // [P, C, C]
        float* __restrict__ dist)           // [B, P]
{
    const int p = blockIdx.x;
    const int t = threadIdx.x;              // 128
    const int w = t >> 5, l = t & 31;

    __shared__ __align__(16) float sd[Cc * SDSTR];
    __shared__ float wsum[4][Bb];

    // coalesced load of delta tile (16KB) into padded smem rows
    {
        const float* src = gdelta + (size_t)p * (Cc * Bb);
        #pragma unroll
        for (int j = 0; j < 8; j++) {
            int fi = (t + 128 * j) << 2;
            int c = fi >> 4, b = fi & 15;
            float4 v = *(const float4*)(src + fi);
            *(float4*)&sd[c * SDSTR + b] = v;
        }
    }
    __syncthreads();

    const int blk = (w + blockIdx.x) & 3;       // rotate blocks across SMSPs
    const int d0  = (blk << 6) + (l << 1);
    const int d1  = d0 + 1;
    const int cp  = (blk << 5) + l;
    const float2* M2 = (const float2*)(icov + (size_t)p * (Cc * Cc));

    unsigned long long accA[8], accB[8];
    #pragma unroll
    for (int j = 0; j < 8; j++) { accA[j] = 0ull; accB[j] = 0ull; }

    const int cmain = blk << 6;

    // main loop: rows strictly above the diagonal block.
    // 8-row chunks: 8 front-batched LDGs (MLP 8) then 8 FMA bodies.
    for (int c0 = 0; c0 < cmain; c0 += 8) {
        float2 mv[8];
        #pragma unroll
        for (int j = 0; j < 8; j++) mv[j] = M2[(c0 + j) * 128 + cp];
        #pragma unroll
        for (int j = 0; j < 8; j++) MMABODY(mv[j].x, mv[j].y, &sd[(c0 + j) * SDSTR]);
    }

    // tail: 64 rows covering the diagonal block. Non-divergent: loads are
    // address-clamped (uniform LDG issue, no replay splits); multipliers get
    // weight {1, 0.5, 0} by position relative to the diagonal.
    #pragma unroll
    for (int c0 = 0; c0 < 64; c0 += 8) {
        float2 mv[8];
        #pragma unroll
        for (int j = 0; j < 8; j++) {
            int c  = cmain + c0 + j;
            int cc = (c <= d1) ? c : d1;        // clamp address, stay in-bounds
            mv[j] = M2[cc * 128 + cp];
        }
        #pragma unroll
        for (int j = 0; j < 8; j++) {
            int c = cmain + c0 + j;
            float sx = (c < d0) ? 1.f : ((c == d0) ? 0.5f : 0.f);
            float sy = (c < d1) ? 1.f : ((c == d1) ? 0.5f : 0.f);
            MMABODY(mv[j].x * sx, mv[j].y * sy, &sd[c * SDSTR]);
        }
    }

    // q[b] = dA[b]*sA[b] + dB[b]*sB[b]
    float q[Bb];
    #pragma unroll
    for (int j = 0; j < 8; j++) {
        float2 fa = *(float2*)&accA[j];
        float2 fb = *(float2*)&accB[j];
        float2 dA = *(const float2*)&sd[d0 * SDSTR + 2 * j];
        float2 dB = *(const float2*)&sd[d1 * SDSTR + 2 * j];
        q[2 * j]     = fa.x * dA.x + fb.x * dB.x;
        q[2 * j + 1] = fa.y * dA.y + fb.y * dB.y;
    }

    #pragma unroll
    for (int off = 16; off > 0; off >>= 1) {
        #pragma unroll
        for (int b = 0; b < Bb; b++)
            q[b] += __shfl_xor_sync(0xffffffffu, q[b], off);
    }
    if (l == 0) {
        #pragma unroll
        for (int b = 0; b < Bb; b++) wsum[w][b] = q[b];
    }
    __syncthreads();
    if (t < Bb) {
        float v = wsum[0][t] + wsum[1][t] + wsum[2][t] + wsum[3][t];
        dist[t * Pp + p] = sqrtf(2.f * v);
    }
}

// ---------------- stage 2: bilinear 56 -> 224 (align_corners=False) --------
__global__ void k_resize(const float* __restrict__ dist, float* __restrict__ out)
{
    int idx = blockIdx.x * blockDim.x + threadIdx.x;
    if (idx >= NPIX) return;
    int X = idx % S_;
    int Y = (idx / S_) % S_;
    int b = idx / (S_ * S_);

    float fy = (float)Y * 0.25f - 0.375f;
    float fx = (float)X * 0.25f - 0.375f;
    int y0 = (int)floorf(fy); float wy = fy - (float)y0;
    int x0 = (int)floorf(fx); float wx = fx - (float)x0;
    int y0c = max(y0, 0), y1c = min(y0 + 1, Hh - 1);
    int x0c = max(x0, 0), x1c = min(x0 + 1, Ww - 1);

    const float* d = dist + b * Pp;
    float v00 = d[y0c * Ww + x0c], v01 = d[y0c * Ww + x1c];
    float v10 = d[y1c * Ww + x0c], v11 = d[y1c * Ww + x1c];
    float v0 = v00 + (v01 - v00) * wx;
    float v1 = v10 + (v11 - v10) * wx;
    out[idx] = v0 + (v1 - v0) * wy;
}

// symmetric padding (numpy 'symmetric' == scipy reflect), radius < 224
__device__ __forceinline__ int symi(int i) {
    i = (i < 0) ? (-1 - i) : i;
    i = (i >= S_) ? (2 * S_ - 1 - i) : i;
    return i;
}

// ---------------- stage 3a: gaussian blur along H ---------------------------
__global__ void k_blurH(const float* __restrict__ in, float* __restrict__ out)
{
    int idx = blockIdx.x * blockDim.x + threadIdx.x;
    if (idx >= NPIX) return;
    int X = idx % S_;
    int Y = (idx / S_) % S_;
    int b = idx / (S_ * S_);
    const float* base = in + b * S_ * S_;
    float v = 0.f;
    #pragma unroll
    for (int k = 0; k < KK; k++) {
        int y = symi(Y + k - R_);
        v = fmaf(g_gw[k], base[y * S_ + X], v);
    }
    out[idx] = v;
}

// ---------------- stage 3b: blur along W + global min/max -------------------
__global__ void k_blurW(const float* __restrict__ in, float* __restrict__ out)
{
    int idx = blockIdx.x * blockDim.x + threadIdx.x;
    int X = idx % S_;
    int Y = (idx / S_) % S_;
    int b = idx / (S_ * S_);
    const float* base = in + b * S_ * S_ + Y * S_;
    float v = 0.f;
    #pragma unroll
    for (int k = 0; k < KK; k++) {
        int x = symi(X + k - R_);
        v = fmaf(g_gw[k], base[x], v);
    }
    out[idx] = v;

    float mn = v, mx = v;
    #pragma unroll
    for (int off = 16; off > 0; off >>= 1) {
        mn = fminf(mn, __shfl_xor_sync(0xffffffffu, mn, off));
        mx = fmaxf(mx, __shfl_xor_sync(0xffffffffu, mx, off));
    }
    __shared__ float smn[8], smx[8];
    int warp = threadIdx.x >> 5, lane = threadIdx.x & 31;
    if (lane == 0) { smn[warp] = mn; smx[warp] = mx; }
    __syncthreads();
    if (threadIdx.x == 0) {
        float bmn = smn[0], bmx = smx[0];
        #pragma unroll
        for (int w = 1; w < 8; w++) {
            bmn = fminf(bmn, smn[w]);
            bmx = fmaxf(bmx, smx[w]);
        }
        atomicMin(&g_minbits, __float_as_int(bmn));   // values >= 0
        atomicMax(&g_maxbits, __float_as_int(bmx));
    }
}

// ---------------- stage 4: normalize ----------------------------------------
__global__ void k_norm(float* __restrict__ out)
{
    int idx = blockIdx.x * blockDim.x + threadIdx.x;
    if (idx >= NPIX) return;
    float mn = __int_as_float(g_minbits);
    float mx = __int_as_float(g_maxbits);
    out[idx] = (out[idx] - mn) / (mx - mn);
}

// ---------------- launcher ---------------------------------------------------
extern "C" void kernel_launch(void* const* d_in, const int* in_sizes, int n_in,
                              void* d_out, int out_size)
{
    const float* emb   = (const float*)d_in[0];   // [16, 256, 3136]
    const float* means = (const float*)d_in[1];   // [3136, 256]
    const float* icov  = (const float*)d_in[2];   // [3136, 256, 256]
    float* out = (float*)d_out;                   // [16, 224, 224] float32

    float *delta = nullptr, *dist = nullptr, *up = nullptr, *tmp = nullptr;
    cudaGetSymbolAddress((void**)&delta, g_delta);
    cudaGetSymbolAddress((void**)&dist,  g_dist);
    cudaGetSymbolAddress((void**)&up,    g_up);
    cudaGetSymbolAddress((void**)&tmp,   g_tmp);

    const int nb = NPIX / 256;
    k_init<<<1, 32>>>();                                      // launch 1
    k_transpose<<<dim3(Pp / PT, Cc / CT), 256>>>(emb, means, delta); // launch 2
    k_init<<<1, 32>>>();   // idempotent filler: puts k_mahal at the captured slot
    k_mahal<<<Pp, 128>>>(delta, icov, dist);                  // launch 4 (profiled)
    k_resize<<<nb, 256>>>(dist, up);
    k_blurH<<<nb, 256>>>(up, tmp);
    k_blurW<<<nb, 256>>>(tmp, out);
    k_norm<<<nb, 256>>>(out);
}

// round 11
// speedup vs baseline: 1.9990x; 1.0442x over previous
#include <cuda_runtime.h>
#include <cstdint>

#define Bb   16
#define Cc   256
#define Pp   3136
#define Hh   56
#define Ww   56
#define S_   224
#define R_   16
#define KK   33
#define NPIX (Bb * S_ * S_)       // 802816
#define SDSTR 20                  // padded smem row stride (floats), 80B

// ---------------- scratch (static device arrays; no runtime allocation) ----
__device__ float g_delta[Pp * Cc * Bb];  // [p][c*16+b]  (51.4 MB)
__device__ float g_dist[Bb * Pp];        // [B,56,56]
__device__ float g_t1[Bb * S_ * Ww];     // [B,224,56] vertical-pass intermediate
__device__ float g_gw[KK];
__device__ int   g_minbits;
__device__ int   g_maxbits;

// ---------------- init: gaussian weights + min/max seeds -------------------
__global__ void k_init() {
    if (threadIdx.x == 0) {
        float w[KK];
        float s = 0.f;
        #pragma unroll
        for (int i = 0; i < KK; i++) {
            float x = (float)(i - R_) * 0.25f;     // x/sigma, sigma=4
            w[i] = expf(-0.5f * x * x);
            s += w[i];
        }
        float inv = 1.f / s;
        #pragma unroll
        for (int i = 0; i < KK; i++) g_gw[i] = w[i] * inv;
        g_minbits = 0x7f7fffff;  // +FLT_MAX  (scores >= 0 -> int-ordered)
        g_maxbits = 0;           // +0.0f
    }
}

// ---------------- stage 0: transpose emb -> delta[p][c*16+b] ----------------
#define PT 32
#define CT 16
__global__ void k_transpose(const float* __restrict__ emb,
                            const float* __restrict__ means,
                            float* __restrict__ gdelta)
{
    __shared__ float ts[PT][CT * 16 + 1];
    const int pb = blockIdx.x * PT;
    const int cb = blockIdx.y * CT;
    const int t = threadIdx.x;              // 256
    const int w = t >> 5, l = t & 31;

    #pragma unroll 4
    for (int j = 0; j < 32; j++) {
        int r  = (w << 5) + j;
        int ci = r >> 4, b = r & 15;
        ts[l][r] = emb[((size_t)(b * Cc + cb + ci)) * Pp + pb + l];
    }
    __syncthreads();

    #pragma unroll 4
    for (int j = 0; j < 32; j++) {
        int g  = t + 256 * j;
        int pl = g >> 8;
        int cf = g & 255;
        int ci = cf >> 4;
        float m = means[(size_t)(pb + pl) * Cc + cb + ci];
        gdelta[((size_t)(pb + pl)) * (Cc * Bb) + (size_t)cb * 16 + cf] =
            ts[pl][cf] - m;
    }
}

// ---------------- stage 1: mahalanobis (symmetric upper triangle) ----------
// q[b] = 2 * sum_d delta[b,d]*(0.5*M[d,d]*delta[b,d] + sum_{c<d} M[c,d]*delta[b,c])
#define FMA2(acc, mm, dd) \
    asm("fma.rn.f32x2 %0, %1, %2, %0;" : "+l"(acc) : "l"(mm), "l"(dd))

#define MMABODY(mvx, mvy, rowptr)                                          \
  { unsigned long long mx, my;                                             \
    asm("mov.b64 %0, {%1, %1};" : "=l"(mx) : "f"(mvx));                    \
    asm("mov.b64 %0, {%1, %1};" : "=l"(my) : "f"(mvy));                    \
    const ulonglong2* rr = (const ulonglong2*)(rowptr);                    \
    ulonglong2 r0 = rr[0], r1 = rr[1], r2 = rr[2], r3 = rr[3];             \
    FMA2(accA[0], mx, r0.x); FMA2(accA[1], mx, r0.y);                      \
    FMA2(accA[2], mx, r1.x); FMA2(accA[3], mx, r1.y);                      \
    FMA2(accA[4], mx, r2.x); FMA2(accA[5], mx, r2.y);                      \
    FMA2(accA[6], mx, r3.x); FMA2(accA[7], mx, r3.y);                      \
    FMA2(accB[0], my, r0.x); FMA2(accB[1], my, r0.y);                      \
    FMA2(accB[2], my, r1.x); FMA2(accB[3], my, r1.y);                      \
    FMA2(accB[4], my, r2.x); FMA2(accB[5], my, r2.y);                      \
    FMA2(accB[6], my, r3.x); FMA2(accB[7], my, r3.y); }

__global__ void __launch_bounds__(128, 6)
k_mahal(const float* __restrict__ gdelta,   // [p][c*16+b]
        const float* __restrict__ icov,     // [P, C, C]
        float* __restrict__ dist)           // [B, P]
{
    const int p = blockIdx.x;
    const int t = threadIdx.x;              // 128
    const int w = t >> 5, l = t & 31;

    __shared__ __align__(16) float sd[Cc * SDSTR];
    __shared__ float wsum[4][Bb];

    // coalesced load of delta tile (16KB) into padded smem rows
    {
        const float* src = gdelta + (size_t)p * (Cc * Bb);
        #pragma unroll
        for (int j = 0; j < 8; j++) {
            int fi = (t + 128 * j) << 2;
            int c = fi >> 4, b = fi & 15;
            float4 v = *(const float4*)(src + fi);
            *(float4*)&sd[c * SDSTR + b] = v;
        }
    }
    __syncthreads();

    const int blk = (w + blockIdx.x) & 3;       // rotate blocks across SMSPs
    const int d0  = (blk << 6) + (l << 1);
    const int d1  = d0 + 1;
    const int cp  = (blk << 5) + l;
    const float2* M2 = (const float2*)(icov + (size_t)p * (Cc * Cc));

    unsigned long long accA[8], accB[8];
    #pragma unroll
    for (int j = 0; j < 8; j++) { accA[j] = 0ull; accB[j] = 0ull; }

    const int cmain = blk << 6;

    // main loop: rows strictly above the diagonal block.
    // 8-row chunks: 8 front-batched LDGs (MLP 8) then 8 FMA bodies.
    for (int c0 = 0; c0 < cmain; c0 += 8) {
        float2 mv[8];
        #pragma unroll
        for (int j = 0; j < 8; j++) mv[j] = M2[(c0 + j) * 128 + cp];
        #pragma unroll
        for (int j = 0; j < 8; j++) MMABODY(mv[j].x, mv[j].y, &sd[(c0 + j) * SDSTR]);
    }

    // tail: 64 rows covering the diagonal block; address-clamped loads,
    // multipliers weighted {1, 0.5, 0} around the diagonal.
    #pragma unroll
    for (int c0 = 0; c0 < 64; c0 += 8) {
        float2 mv[8];
        #pragma unroll
        for (int j = 0; j < 8; j++) {
            int c  = cmain + c0 + j;
            int cc = (c <= d1) ? c : d1;
            mv[j] = M2[cc * 128 + cp];
        }
        #pragma unroll
        for (int j = 0; j < 8; j++) {
            int c = cmain + c0 + j;
            float sx = (c < d0) ? 1.f : ((c == d0) ? 0.5f : 0.f);
            float sy = (c < d1) ? 1.f : ((c == d1) ? 0.5f : 0.f);
            MMABODY(mv[j].x * sx, mv[j].y * sy, &sd[c * SDSTR]);
        }
    }

    // q[b] = dA[b]*sA[b] + dB[b]*sB[b]
    float q[Bb];
    #pragma unroll
    for (int j = 0; j < 8; j++) {
        float2 fa = *(float2*)&accA[j];
        float2 fb = *(float2*)&accB[j];
        float2 dA = *(const float2*)&sd[d0 * SDSTR + 2 * j];
        float2 dB = *(const float2*)&sd[d1 * SDSTR + 2 * j];
        q[2 * j]     = fa.x * dA.x + fb.x * dB.x;
        q[2 * j + 1] = fa.y * dA.y + fb.y * dB.y;
    }

    #pragma unroll
    for (int off = 16; off > 0; off >>= 1) {
        #pragma unroll
        for (int b = 0; b < Bb; b++)
            q[b] += __shfl_xor_sync(0xffffffffu, q[b], off);
    }
    if (l == 0) {
        #pragma unroll
        for (int b = 0; b < Bb; b++) wsum[w][b] = q[b];
    }
    __syncthreads();
    if (t < Bb) {
        float v = wsum[0][t] + wsum[1][t] + wsum[2][t] + wsum[3][t];
        dist[t * Pp + p] = sqrtf(2.f * v);
    }
}

// symmetric padding (numpy 'symmetric' == scipy reflect), radius < 224
__device__ __forceinline__ int symi(int i) {
    i = (i < 0) ? (-1 - i) : i;
    i = (i >= S_) ? (2 * S_ - 1 - i) : i;
    return i;
}

// ---------------- stage 2: fused vertical (upsample-y + blur-y) -------------
// T1[b, Y, x] = sum_k g[k] * Uy(dist_b)(symi(Y+k-R), x)
// Valid because Gy.Uy commutes with Gx.Ux (independent axes, linear ops).
__global__ void k_vblur(const float* __restrict__ dist, float* __restrict__ t1)
{
    int idx = blockIdx.x * blockDim.x + threadIdx.x;
    if (idx >= Bb * S_ * Ww) return;
    int x = idx % Ww;
    int Y = (idx / Ww) % S_;
    int b = idx / (Ww * S_);
    const float* d = dist + b * Pp;

    float v = 0.f;
    #pragma unroll
    for (int k = 0; k < KK; k++) {
        int yy = symi(Y + k - R_);
        float fy = (float)yy * 0.25f - 0.375f;
        int y0 = (int)floorf(fy);
        float wy = fy - (float)y0;
        int y0c = max(y0, 0), y1c = min(y0 + 1, Hh - 1);
        float a = d[y0c * Ww + x];
        float c = d[y1c * Ww + x];
        v = fmaf(g_gw[k], a + (c - a) * wy, v);
    }
    t1[idx] = v;
}

// ---------------- stage 3: fused horizontal (upsample-x + blur-x) + min/max -
__global__ void k_hblur(const float* __restrict__ t1, float* __restrict__ out)
{
    int idx = blockIdx.x * blockDim.x + threadIdx.x;
    int X = idx % S_;
    int Y = (idx / S_) % S_;
    int b = idx / (S_ * S_);
    const float* base = t1 + (b * S_ + Y) * Ww;

    float v = 0.f;
    #pragma unroll
    for (int k = 0; k < KK; k++) {
        int xx = symi(X + k - R_);
        float fx = (float)xx * 0.25f - 0.375f;
        int x0 = (int)floorf(fx);
        float wx = fx - (float)x0;
        int x0c = max(x0, 0), x1c = min(x0 + 1, Ww - 1);
        float a = base[x0c];
        float c = base[x1c];
        v = fmaf(g_gw[k], a + (c - a) * wx, v);
    }
    out[idx] = v;

    // block min/max (NPIX % 256 == 0 -> all threads valid)
    float mn = v, mx = v;
    #pragma unroll
    for (int off = 16; off > 0; off >>= 1) {
        mn = fminf(mn, __shfl_xor_sync(0xffffffffu, mn, off));
        mx = fmaxf(mx, __shfl_xor_sync(0xffffffffu, mx, off));
    }
    __shared__ float smn[8], smx[8];
    int warp = threadIdx.x >> 5, lane = threadIdx.x & 31;
    if (lane == 0) { smn[warp] = mn; smx[warp] = mx; }
    __syncthreads();
    if (threadIdx.x == 0) {
        float bmn = smn[0], bmx = smx[0];
        #pragma unroll
        for (int w = 1; w < 8; w++) {
            bmn = fminf(bmn, smn[w]);
            bmx = fmaxf(bmx, smx[w]);
        }
        atomicMin(&g_minbits, __float_as_int(bmn));   // values >= 0
        atomicMax(&g_maxbits, __float_as_int(bmx));
    }
}

// ---------------- stage 4: normalize ----------------------------------------
__global__ void k_norm(float* __restrict__ out)
{
    int idx = blockIdx.x * blockDim.x + threadIdx.x;
    if (idx >= NPIX) return;
    float mn = __int_as_float(g_minbits);
    float mx = __int_as_float(g_maxbits);
    out[idx] = (out[idx] - mn) / (mx - mn);
}

// ---------------- launcher ---------------------------------------------------
extern "C" void kernel_launch(void* const* d_in, const int* in_sizes, int n_in,
                              void* d_out, int out_size)
{
    const float* emb   = (const float*)d_in[0];   // [16, 256, 3136]
    const float* means = (const float*)d_in[1];   // [3136, 256]
    const float* icov  = (const float*)d_in[2];   // [3136, 256, 256]
    float* out = (float*)d_out;                   // [16, 224, 224] float32

    float *delta = nullptr, *dist = nullptr, *t1 = nullptr;
    cudaGetSymbolAddress((void**)&delta, g_delta);
    cudaGetSymbolAddress((void**)&dist,  g_dist);
    cudaGetSymbolAddress((void**)&t1,    g_t1);

    const int nb  = NPIX / 256;
    const int nv  = (Bb * S_ * Ww + 255) / 256;
    k_init<<<1, 32>>>();                                      // launch 1
    k_transpose<<<dim3(Pp / PT, Cc / CT), 256>>>(emb, means, delta); // launch 2
    k_init<<<1, 32>>>();   // idempotent filler: keeps k_mahal at the captured slot
    k_mahal<<<Pp, 128>>>(delta, icov, dist);                  // launch 4 (profiled)
    k_vblur<<<nv, 256>>>(dist, t1);
    k_hblur<<<nb, 256>>>(t1, out);
    k_norm<<<nb, 256>>>(out);
}